// round 3
// baseline (speedup 1.0000x reference)
#include <cuda_runtime.h>
#include <cuda_bf16.h>
#include <math_constants.h>

#define BB 4
#define KK 8192
#define G 31
#define CELLS (G * G * G)          // 29791
#define NSB 8                      // (side, batch) combos: side 0=pred, 1=target
#define ORG (-6.2f)
#define H 0.4f
#define INV_H 2.5f
#define QTHREADS 256
#define RTHREADS 1024

// Static scratch (no allocs allowed).
__device__ int          g_cnt[NSB * CELLS];
__device__ int          g_cur[NSB * CELLS];   // scatter cursors (= exclusive starts)
__device__ unsigned int g_bins[NSB * CELLS];  // start<<16 | count
__device__ float4       g_pts[NSB * KK];      // cell-sorted points, w = orig idx bits
__device__ float        g_minv[2][BB * KK];   // per-point NN distance by orig idx

__device__ __forceinline__ int clampc(int c) { return min(G - 1, max(0, c)); }
__device__ __forceinline__ int cix(float v) { return clampc((int)((v - ORG) * INV_H)); }

__global__ void zero_kernel() {
    int i = blockIdx.x * blockDim.x + threadIdx.x;
    if (i < NSB * CELLS) g_cnt[i] = 0;
}

__global__ void count_kernel(const float* __restrict__ pred,
                             const float* __restrict__ target) {
    int i = blockIdx.x * blockDim.x + threadIdx.x;
    if (i >= 2 * BB * KK) return;
    int side = i / (BB * KK);
    int r = i - side * (BB * KK);
    const float* src = side ? target : pred;
    float x = src[r * 3 + 0], y = src[r * 3 + 1], z = src[r * 3 + 2];
    int cell = (cix(z) * G + cix(y)) * G + cix(x);
    int sb = side * BB + r / KK;
    atomicAdd(&g_cnt[sb * CELLS + cell], 1);
}

__global__ void __launch_bounds__(RTHREADS)
prefix_kernel() {
    const int sb = blockIdx.x;
    const int base = sb * CELLS;
    __shared__ int warp_tot[32];
    __shared__ int s_carry;
    if (threadIdx.x == 0) s_carry = 0;
    __syncthreads();
    const int lane = threadIdx.x & 31, wid = threadIdx.x >> 5;
    for (int c0 = 0; c0 < CELLS; c0 += RTHREADS) {
        int idx = c0 + threadIdx.x;
        int v = (idx < CELLS) ? g_cnt[base + idx] : 0;
        int incl = v;
#pragma unroll
        for (int o = 1; o < 32; o <<= 1) {
            int n = __shfl_up_sync(0xFFFFFFFFu, incl, o);
            if (lane >= o) incl += n;
        }
        if (lane == 31) warp_tot[wid] = incl;
        __syncthreads();
        if (wid == 0) {
            int w = warp_tot[lane];
#pragma unroll
            for (int o = 1; o < 32; o <<= 1) {
                int n = __shfl_up_sync(0xFFFFFFFFu, w, o);
                if (lane >= o) w += n;
            }
            warp_tot[lane] = w;
        }
        __syncthreads();
        int carry = s_carry;
        int excl = carry + (wid ? warp_tot[wid - 1] : 0) + incl - v;
        if (idx < CELLS) {
            g_cur[base + idx] = excl;
            g_bins[base + idx] = ((unsigned)excl << 16) | (unsigned)v;
        }
        __syncthreads();
        if (threadIdx.x == RTHREADS - 1) s_carry = excl + v;
        __syncthreads();
    }
}

__global__ void scatter_kernel(const float* __restrict__ pred,
                               const float* __restrict__ target) {
    int i = blockIdx.x * blockDim.x + threadIdx.x;
    if (i >= 2 * BB * KK) return;
    int side = i / (BB * KK);
    int r = i - side * (BB * KK);
    const float* src = side ? target : pred;
    float x = src[r * 3 + 0], y = src[r * 3 + 1], z = src[r * 3 + 2];
    int cell = (cix(z) * G + cix(y)) * G + cix(x);
    int sb = side * BB + r / KK;
    int slot = atomicAdd(&g_cur[sb * CELLS + cell], 1);
    g_pts[sb * KK + slot] = make_float4(x, y, z, __int_as_float(r % KK));
}

// One thread per query (cell-sorted order => warp-coherent neighborhoods).
__global__ void __launch_bounds__(QTHREADS)
query_kernel() {
    const int dir = blockIdx.z;  // 0: query=pred, db=target; 1: swapped
    const int b = blockIdx.y;
    const int qi = blockIdx.x * QTHREADS + threadIdx.x;
    const int qsb = (dir ? 1 : 0) * BB + b;
    const int dsb = (dir ? 0 : 1) * BB + b;

    const float4 q = g_pts[qsb * KK + qi];
    const int orig = __float_as_int(q.w);
    const unsigned int* __restrict__ bins = &g_bins[dsb * CELLS];
    const float4* __restrict__ pts = &g_pts[dsb * KK];

    const int c0x = cix(q.x), c0y = cix(q.y), c0z = cix(q.z);
    float best2 = CUDART_INF_F;

    auto scan_row = [&](int cz, int cy, int x0, int x1) {
        int rowbase = (cz * G + cy) * G;
        unsigned pL = bins[rowbase + x0];
        unsigned pR = bins[rowbase + x1];
        int p = (int)(pL >> 16);
        int e = (int)(pR >> 16) + (int)(pR & 0xFFFFu);
#pragma unroll 4
        for (; p < e; p++) {
            float4 t = pts[p];
            float dx = q.x - t.x, dy = q.y - t.y, dz = q.z - t.z;
            float d2 = fmaf(dx, dx, fmaf(dy, dy, dz * dz));
            best2 = fminf(best2, d2);
        }
    };

    // Rings 0..1 as a single box.
    {
        int zlo = max(c0z - 1, 0), zhi = min(c0z + 1, G - 1);
        int ylo = max(c0y - 1, 0), yhi = min(c0y + 1, G - 1);
        int xlo = max(c0x - 1, 0), xhi = min(c0x + 1, G - 1);
        for (int cz = zlo; cz <= zhi; cz++)
            for (int cy = ylo; cy <= yhi; cy++)
                scan_row(cz, cy, xlo, xhi);
    }

    // Expand rings: after scanning ring s, points in ring s+1 are >= s*H away.
    int s = 1;
    while (best2 > (s * H) * (s * H) && s < G) {
        s++;
        int zlo = max(c0z - s, 0), zhi = min(c0z + s, G - 1);
        int ylo = max(c0y - s, 0), yhi = min(c0y + s, G - 1);
        int xlo = max(c0x - s, 0), xhi = min(c0x + s, G - 1);
        for (int cz = zlo; cz <= zhi; cz++) {
            for (int cy = ylo; cy <= yhi; cy++) {
                bool edge = (cz == c0z - s) || (cz == c0z + s) ||
                            (cy == c0y - s) || (cy == c0y + s);
                if (edge) {
                    scan_row(cz, cy, xlo, xhi);
                } else {
                    if (c0x - s >= 0) scan_row(cz, cy, c0x - s, c0x - s);
                    if (c0x + s <= G - 1) scan_row(cz, cy, c0x + s, c0x + s);
                }
            }
        }
    }

    g_minv[dir][b * KK + orig] = sqrtf(fmaxf(best2, 0.0f));
}

// Single-block fused reduction: deterministic fixed-order sums.
__global__ void __launch_bounds__(RTHREADS)
reduce_kernel(const float* __restrict__ mask, float* __restrict__ out) {
    float s0 = 0.f, s1 = 0.f, s2 = 0.f;
    for (int i = threadIdx.x; i < BB * KK; i += RTHREADS) {
        float mk = mask[i];
        s0 = fmaf(g_minv[0][i], mk, s0);
        s1 = fmaf(g_minv[1][i], mk, s1);
        s2 += mk;
    }
    __shared__ float sh[3][RTHREADS];
    const int tid = threadIdx.x;
    sh[0][tid] = s0; sh[1][tid] = s1; sh[2][tid] = s2;
    __syncthreads();
    for (int off = RTHREADS / 2; off > 0; off >>= 1) {
        if (tid < off) {
            sh[0][tid] += sh[0][tid + off];
            sh[1][tid] += sh[1][tid + off];
            sh[2][tid] += sh[2][tid + off];
        }
        __syncthreads();
    }
    if (tid == 0)
        out[0] = (sh[0][0] + sh[1][0]) / (2.0f * (sh[2][0] + 1e-8f));
}

extern "C" void kernel_launch(void* const* d_in, const int* in_sizes, int n_in,
                              void* d_out, int out_size) {
    const float* pred   = (const float*)d_in[0];
    const float* target = (const float*)d_in[1];
    const float* mask   = (const float*)d_in[2];
    float* out = (float*)d_out;

    zero_kernel<<<(NSB * CELLS + 1023) / 1024, 1024>>>();
    count_kernel<<<(2 * BB * KK + 255) / 256, 256>>>(pred, target);
    prefix_kernel<<<NSB, RTHREADS>>>();
    scatter_kernel<<<(2 * BB * KK + 255) / 256, 256>>>(pred, target);

    dim3 qgrid(KK / QTHREADS, BB, 2);
    query_kernel<<<qgrid, QTHREADS>>>();

    reduce_kernel<<<1, RTHREADS>>>(mask, out);
}

// round 4
// speedup vs baseline: 1.0788x; 1.0788x over previous
#include <cuda_runtime.h>
#include <cuda_bf16.h>
#include <math_constants.h>

#define BB 4
#define KK 8192
#define THREADS 256
#define RM 8
#define ROWSB (THREADS * RM)       // 2048 rows per block
#define TN 512                     // cols per block (= KK/NSPLIT)
#define NSPLIT 16
#define NWARP (THREADS / 32)
#define RTHREADS 1024

// Scratch (no allocs): per-point min DISTANCE as order-preserving uint bits.
// [0] = per-pred (row mins), [1] = per-target (col mins).
__device__ unsigned int g_min[2][BB * KK];

__global__ void init_kernel() {
    int i = blockIdx.x * blockDim.x + threadIdx.x;
    if (i < 2 * BB * KK) ((unsigned int*)g_min)[i] = 0x7F800000u;  // +inf
}

// One pass over the pair matrix serves BOTH chamfer directions:
//   u_ij = 0.5*|p_i - t_j|^2 = (0.5*p_i^2 + 0.5*t_j^2) - p_i.t_j
// row-min(u) -> nearest target per pred; col-min(u) -> nearest pred per target.
__global__ void __launch_bounds__(THREADS)
chamfer_fused_kernel(const float* __restrict__ pred,
                     const float* __restrict__ target) {
    const int b       = blockIdx.y;
    const int rowtile = blockIdx.x / NSPLIT;
    const int jsplit  = blockIdx.x % NSPLIT;
    const int tid     = threadIdx.x;
    const int lane    = tid & 31;
    const int wid     = tid >> 5;

    __shared__ float4 sh[TN];             // target tile: x,y,z, 0.5*t^2
    __shared__ float  colm[NWARP][TN];    // per-warp col-min partials

    // Per-thread rows (pred points).
    float nx[RM], ny[RM], nz[RM], h[RM], m[RM];
    const int ibase = rowtile * ROWSB + tid;
#pragma unroll
    for (int r = 0; r < RM; r++) {
        const int i = ibase + r * THREADS;
        const float* p = pred + ((size_t)b * KK + i) * 3;
        float x = p[0], y = p[1], z = p[2];
        nx[r] = -x; ny[r] = -y; nz[r] = -z;
        h[r]  = 0.5f * (x * x + y * y + z * z);
        m[r]  = CUDART_INF_F;
    }

    // Load target tile (512 pts = 2 per thread).
    const int j0 = jsplit * TN;
#pragma unroll
    for (int u = 0; u < TN / THREADS; u++) {
        const int j = tid + u * THREADS;
        const float* t = target + ((size_t)b * KK + j0 + j) * 3;
        float x = t[0], y = t[1], z = t[2];
        sh[j] = make_float4(x, y, z, 0.5f * (x * x + y * y + z * z));
    }
    __syncthreads();

#pragma unroll 2
    for (int j = 0; j < TN; j++) {
        const float4 t = sh[j];
        float c = CUDART_INF_F;
#pragma unroll
        for (int r = 0; r < RM; r++) {
            float s = t.w + h[r];
            s = fmaf(nx[r], t.x, s);
            s = fmaf(ny[r], t.y, s);
            s = fmaf(nz[r], t.z, s);
            m[r] = fminf(m[r], s);
            c = fminf(c, s);
        }
        // warp-min of col candidate (all lanes at same j; no divergence)
#pragma unroll
        for (int off = 16; off > 0; off >>= 1)
            c = fminf(c, __shfl_xor_sync(0xFFFFFFFFu, c, off));
        if (lane == 0) colm[wid][j] = c;
    }

    // Row results: d = sqrt(2u), combine across j-splits via atomicMin.
#pragma unroll
    for (int r = 0; r < RM; r++) {
        float d = sqrtf(fmaxf(2.0f * m[r], 0.0f));
        atomicMin(&g_min[0][(size_t)b * KK + ibase + r * THREADS],
                  __float_as_uint(d));
    }

    // Col results: reduce the 8 warp partials, combine across row-tiles.
    __syncthreads();
    for (int j = tid; j < TN; j += THREADS) {
        float c = colm[0][j];
#pragma unroll
        for (int w = 1; w < NWARP; w++) c = fminf(c, colm[w][j]);
        float d = sqrtf(fmaxf(2.0f * c, 0.0f));
        atomicMin(&g_min[1][(size_t)b * KK + j0 + j], __float_as_uint(d));
    }
}

// Single-block fused reduction: deterministic fixed-order sums.
__global__ void __launch_bounds__(RTHREADS)
reduce_kernel(const float* __restrict__ mask, float* __restrict__ out) {
    float s0 = 0.f, s1 = 0.f, s2 = 0.f;
    for (int i = threadIdx.x; i < BB * KK; i += RTHREADS) {
        float mk = mask[i];
        s0 = fmaf(__uint_as_float(g_min[0][i]), mk, s0);
        s1 = fmaf(__uint_as_float(g_min[1][i]), mk, s1);
        s2 += mk;
    }
    __shared__ float sh[3][RTHREADS];
    const int tid = threadIdx.x;
    sh[0][tid] = s0; sh[1][tid] = s1; sh[2][tid] = s2;
    __syncthreads();
    for (int off = RTHREADS / 2; off > 0; off >>= 1) {
        if (tid < off) {
            sh[0][tid] += sh[0][tid + off];
            sh[1][tid] += sh[1][tid + off];
            sh[2][tid] += sh[2][tid + off];
        }
        __syncthreads();
    }
    if (tid == 0)
        out[0] = (sh[0][0] + sh[1][0]) / (2.0f * (sh[2][0] + 1e-8f));
}

extern "C" void kernel_launch(void* const* d_in, const int* in_sizes, int n_in,
                              void* d_out, int out_size) {
    const float* pred   = (const float*)d_in[0];
    const float* target = (const float*)d_in[1];
    const float* mask   = (const float*)d_in[2];
    float* out = (float*)d_out;

    init_kernel<<<(2 * BB * KK + 1023) / 1024, 1024>>>();

    dim3 grid((KK / ROWSB) * NSPLIT, BB);   // 64 x 4 = 256 blocks
    chamfer_fused_kernel<<<grid, THREADS>>>(pred, target);

    reduce_kernel<<<1, RTHREADS>>>(mask, out);
}

// round 5
// speedup vs baseline: 1.2425x; 1.1518x over previous
#include <cuda_runtime.h>
#include <cuda_bf16.h>
#include <math_constants.h>

#define BB 4
#define KK 8192
#define THREADS 256
#define RM 8              // rows per thread  (ty: 8  -> 64 rows/block)
#define CN 4              // cols per thread/pass (tx: 32 -> 128 cols/pass)
#define ROWS_B 64
#define COLS_P 128
#define COLHALF 4096
#define NPASS (COLHALF / COLS_P)   // 32
#define RTHREADS 1024

// Scratch: per-point min of u = 0.5*|p-t|^2 as order-preserving uint bits
// (u clamped >= 0 before conversion). [0] = per-pred row mins, [1] = per-target col mins.
__device__ unsigned int g_min[2][BB * KK];

__global__ void init_kernel() {
    int i = blockIdx.x * blockDim.x + threadIdx.x;
    if (i < 2 * BB * KK) ((unsigned int*)g_min)[i] = 0x7F800000u;  // +inf
}

// One pass over the pair matrix serves BOTH directions.
// u_ij = h_i + w_ij,  w_ij = tw_j - p_i.t_j,  h = 0.5|p|^2, tw = 0.5|t|^2.
// Row mins: track w in regs (h const per row). Col mins: u per pair, flushed per pass.
__global__ void __launch_bounds__(THREADS)
chamfer_kernel(const float* __restrict__ pred, const float* __restrict__ target) {
    const int b       = blockIdx.z;
    const int rowblk  = blockIdx.x;
    const int colbase = blockIdx.y * COLHALF;
    const int tid = threadIdx.x;
    const int tx = tid & 31, ty = tid >> 5;

    __shared__ float4 tile[2][COLS_P];        // x,y,z, 0.5*t^2
    __shared__ float  scol[2][8][COLS_P];     // per-ty col partials

    float nx[RM], ny[RM], nz[RM], h[RM], m[RM];
    const int row0 = rowblk * ROWS_B + ty * RM;
    const float* pr = pred + ((size_t)b * KK + row0) * 3;
#pragma unroll
    for (int r = 0; r < RM; r++) {
        float x = pr[r * 3], y = pr[r * 3 + 1], z = pr[r * 3 + 2];
        nx[r] = -x; ny[r] = -y; nz[r] = -z;
        h[r] = 0.5f * (x * x + y * y + z * z);
        m[r] = CUDART_INF_F;
    }

    const float* tg = target + ((size_t)b * KK + colbase) * 3;
    if (tid < COLS_P) {
        float x = tg[tid * 3], y = tg[tid * 3 + 1], z = tg[tid * 3 + 2];
        tile[0][tid] = make_float4(x, y, z, 0.5f * (x * x + y * y + z * z));
    }
    __syncthreads();

    for (int pass = 0; pass < NPASS; pass++) {
        const int buf = pass & 1;
        // Prefetch next tile into the other buffer.
        if (pass + 1 < NPASS && tid < COLS_P) {
            const float* t2 = tg + ((pass + 1) * COLS_P + tid) * 3;
            float x = t2[0], y = t2[1], z = t2[2];
            tile[buf ^ 1][tid] = make_float4(x, y, z, 0.5f * (x * x + y * y + z * z));
        }

        float4 cp[CN];
#pragma unroll
        for (int c = 0; c < CN; c++) cp[c] = tile[buf][tx + 32 * c];
        float cpart[CN];
#pragma unroll
        for (int c = 0; c < CN; c++) cpart[c] = CUDART_INF_F;

#pragma unroll
        for (int c = 0; c < CN; c++) {
#pragma unroll
            for (int r = 0; r < RM; r++) {
                float w = fmaf(nz[r], cp[c].z, cp[c].w);
                w = fmaf(ny[r], cp[c].y, w);
                w = fmaf(nx[r], cp[c].x, w);
                m[r] = fminf(m[r], w);
                float u;  // u = w*1.0 + h : FFMA-imm form (rt=1) instead of FADD (rt=2)
                asm("fma.rn.f32 %0, %1, 0f3F800000, %2;" : "=f"(u) : "f"(w), "f"(h[r]));
                cpart[c] = fminf(cpart[c], u);
            }
        }

#pragma unroll
        for (int c = 0; c < CN; c++) scol[buf][ty][tx + 32 * c] = cpart[c];
        __syncthreads();

        // Flush this pass's 128 cols (each col touched exactly once per block).
        if (tid < COLS_P) {
            float v = scol[buf][0][tid];
#pragma unroll
            for (int t = 1; t < 8; t++) v = fminf(v, scol[buf][t][tid]);
            v = fmaxf(v, 0.0f);
            atomicMin(&g_min[1][(size_t)b * KK + colbase + pass * COLS_P + tid],
                      __float_as_uint(v));
        }
    }

    // Row finalize: one shuffle tree per kernel (lanes cover disjoint cols).
#pragma unroll
    for (int r = 0; r < RM; r++) {
        float w = m[r];
#pragma unroll
        for (int off = 16; off > 0; off >>= 1)
            w = fminf(w, __shfl_xor_sync(0xFFFFFFFFu, w, off));
        if (tx == 0) {
            float u = fmaxf(w + h[r], 0.0f);
            atomicMin(&g_min[0][(size_t)b * KK + row0 + r], __float_as_uint(u));
        }
    }
}

// Single-block fused reduction: deterministic fixed-order sums. d = sqrt(2u).
__global__ void __launch_bounds__(RTHREADS)
reduce_kernel(const float* __restrict__ mask, float* __restrict__ out) {
    float s0 = 0.f, s1 = 0.f, s2 = 0.f;
    for (int i = threadIdx.x; i < BB * KK; i += RTHREADS) {
        float mk = mask[i];
        float u0 = __uint_as_float(g_min[0][i]);
        float u1 = __uint_as_float(g_min[1][i]);
        s0 = fmaf(sqrtf(2.0f * u0), mk, s0);
        s1 = fmaf(sqrtf(2.0f * u1), mk, s1);
        s2 += mk;
    }
    __shared__ float sh[3][RTHREADS];
    const int tid = threadIdx.x;
    sh[0][tid] = s0; sh[1][tid] = s1; sh[2][tid] = s2;
    __syncthreads();
    for (int off = RTHREADS / 2; off > 0; off >>= 1) {
        if (tid < off) {
            sh[0][tid] += sh[0][tid + off];
            sh[1][tid] += sh[1][tid + off];
            sh[2][tid] += sh[2][tid + off];
        }
        __syncthreads();
    }
    if (tid == 0)
        out[0] = (sh[0][0] + sh[1][0]) / (2.0f * (sh[2][0] + 1e-8f));
}

extern "C" void kernel_launch(void* const* d_in, const int* in_sizes, int n_in,
                              void* d_out, int out_size) {
    const float* pred   = (const float*)d_in[0];
    const float* target = (const float*)d_in[1];
    const float* mask   = (const float*)d_in[2];
    float* out = (float*)d_out;

    init_kernel<<<(2 * BB * KK + 1023) / 1024, 1024>>>();

    dim3 grid(KK / ROWS_B, KK / COLHALF, BB);   // 128 x 2 x 4 = 1024 blocks
    chamfer_kernel<<<grid, THREADS>>>(pred, target);

    reduce_kernel<<<1, RTHREADS>>>(mask, out);
}